// round 2
// baseline (speedup 1.0000x reference)
#include <cuda_runtime.h>
#include <cuda_bf16.h>
#include <math.h>

#define H 1024
#define W 1024
#define R 16
#define BIGF 1e10f
#define SENT (1 << 30)

// Intermediate: per-row squared distance to nearest zero (pass 1 output)
__device__ float g_f2[H * W];

// ---------------------------------------------------------------------------
// Pass 1: per-row 1-D squared distance to nearest zero along the row.
// One block (1024 threads) per row. Hillis-Steele scans of nearest-zero index
// (running max going left->right, running min going right->left), exactly
// matching the reference's int arithmetic. Ping-pong buffers -> single
// __syncthreads per scan step.
// ---------------------------------------------------------------------------
__global__ void row_dist_kernel(const float* __restrict__ img) {
    __shared__ int sl[2][W];
    __shared__ int sr[2][W];

    const int row = blockIdx.x;
    const int j = threadIdx.x;

    const float v = img[row * W + j];
    const bool is_zero = (v == 0.0f);
    sl[0][j] = is_zero ? j : -SENT;
    sr[0][j] = is_zero ? j : SENT;
    __syncthreads();

    int p = 0;
    #pragma unroll
    for (int off = 1; off < W; off <<= 1) {
        const int a = (j >= off) ? sl[p][j - off] : -SENT;
        const int b = (j + off < W) ? sr[p][j + off] : SENT;
        sl[p ^ 1][j] = max(sl[p][j], a);
        sr[p ^ 1][j] = min(sr[p][j], b);
        p ^= 1;
        __syncthreads();
    }

    const int d = min(j - sl[p][j], sr[p][j] - j);  // >=2^29 if no zero in row
    const float df = (float)d;
    g_f2[row * W + j] = (d >= (1 << 29)) ? BIGF : df * df;
}

// ---------------------------------------------------------------------------
// Pass 2: out[i,j] = sqrt( min_k f2[k,j] + (i-k)^2 ).
// Windowed exact min: m = min_{|d|<=R} f2[i+d,j] + d^2.  If m <= R^2 then for
// any |i-k| > R we have (i-k)^2 >= (R+1)^2 > R^2 >= m, so m is the global
// minimum (exact).  Otherwise, fall back to a full column scan (exact, rare).
// Shared-memory tile: TI rows x TJ cols with 2R-row halo.
// ---------------------------------------------------------------------------
#define TI 64
#define TJ 32
#define TY 8

__global__ void col_parabola_kernel(float* __restrict__ out) {
    __shared__ float s[TI + 2 * R][TJ];  // 96 x 32 floats = 12 KB

    const int j = blockIdx.x * TJ + threadIdx.x;   // column (0..1023)
    const int i0 = blockIdx.y * TI;                // base row of tile
    const int tx = threadIdx.x;                    // 0..31
    const int ty = threadIdx.y;                    // 0..7

    // Cooperative halo load (clamped rows padded with BIG; BIG never wins
    // unless everything is BIG, in which case the fallback path fires).
    for (int r = ty; r < TI + 2 * R; r += TY) {
        const int gi = i0 + r - R;
        float v = BIGF;
        if (gi >= 0 && gi < H) v = g_f2[gi * W + j];
        s[r][tx] = v;
    }
    __syncthreads();

    #pragma unroll
    for (int rr = 0; rr < TI / TY; rr++) {
        const int li = ty + rr * TY;     // local row in [0, TI)
        const int i = i0 + li;

        float m = s[li][tx] + (float)(R * R);  // d = -R tap
        #pragma unroll
        for (int d = -R + 1; d <= R; d++) {
            m = fminf(m, s[li + R + d][tx] + (float)(d * d));
        }

        if (m > (float)(R * R)) {
            // Exact fallback: full-column parabola min (rare).
            m = 3.4e38f;
            for (int k = 0; k < H; k++) {
                const float di = (float)(i - k);
                m = fminf(m, g_f2[k * W + j] + di * di);
            }
        }

        out[i * W + j] = sqrtf(m);
    }
}

// ---------------------------------------------------------------------------
extern "C" void kernel_launch(void* const* d_in, const int* in_sizes, int n_in,
                              void* d_out, int out_size) {
    const float* img = (const float*)d_in[0];
    float* out = (float*)d_out;

    row_dist_kernel<<<H, W>>>(img);

    dim3 block(TJ, TY);
    dim3 grid(W / TJ, H / TI);
    col_parabola_kernel<<<grid, block>>>(out);
}

// round 3
// speedup vs baseline: 1.3743x; 1.3743x over previous
#include <cuda_runtime.h>
#include <cuda_bf16.h>
#include <math.h>

#define H 1024
#define W 1024
#define R 16
#define BIGF 1e10f
#define SENT (1 << 30)

// Intermediate: per-row squared distance to nearest zero (pass 1 output)
__device__ float g_f2[H * W];

// ---------------------------------------------------------------------------
// Pass 1: per-row 1-D squared distance to nearest zero along the row.
// One block (1024 threads) per row. Hierarchical scan: warp-level shfl
// max/min scans + one 32-aggregate exchange. Only 2 block barriers.
// ---------------------------------------------------------------------------
__global__ void row_dist_kernel(const float* __restrict__ img) {
    __shared__ int wl[32], wr[32];    // per-warp inclusive aggregates
    __shared__ int wle[32], wre[32];  // exclusive cross-warp prefixes

    const int row = blockIdx.x;
    const int j = threadIdx.x;
    const int lane = j & 31;
    const int warp = j >> 5;

    const bool is_zero = (img[row * W + j] == 0.0f);
    int zl = is_zero ? j : -SENT;  // nearest zero index to the left (running max)
    int zr = is_zero ? j : SENT;   // nearest zero index to the right (running min)

    // Warp-local inclusive scans.
    #pragma unroll
    for (int o = 1; o < 32; o <<= 1) {
        int v = __shfl_up_sync(0xffffffffu, zl, o);
        if (lane >= o) zl = max(zl, v);
    }
    #pragma unroll
    for (int o = 1; o < 32; o <<= 1) {
        int v = __shfl_down_sync(0xffffffffu, zr, o);
        if (lane < 32 - o) zr = min(zr, v);
    }

    if (lane == 31) wl[warp] = zl;
    if (lane == 0)  wr[warp] = zr;
    __syncthreads();

    // Warp 0 scans the 32 aggregates, producing exclusive prefixes.
    if (warp == 0) {
        int a = wl[lane];
        int b = wr[lane];
        #pragma unroll
        for (int o = 1; o < 32; o <<= 1) {
            int v = __shfl_up_sync(0xffffffffu, a, o);
            if (lane >= o) a = max(a, v);
            int u = __shfl_down_sync(0xffffffffu, b, o);
            if (lane < 32 - o) b = min(b, u);
        }
        int ae = __shfl_up_sync(0xffffffffu, a, 1);
        if (lane == 0) ae = -SENT;
        int be = __shfl_down_sync(0xffffffffu, b, 1);
        if (lane == 31) be = SENT;
        wle[lane] = ae;
        wre[lane] = be;
    }
    __syncthreads();

    zl = max(zl, wle[warp]);
    zr = min(zr, wre[warp]);

    const int d = min(j - zl, zr - j);  // >= 2^29 if no zero in row
    const float df = (float)d;
    g_f2[row * W + j] = (d >= (1 << 29)) ? BIGF : df * df;
}

// ---------------------------------------------------------------------------
// Pass 2: out[i,j] = sqrt( min_k f2[k,j] + (i-k)^2 ).
// Taps expand outward from d=0; warp-voted early exit: once m <= (d+1)^2,
// every remaining tap contributes >= (d+1)^2 >= m -> stop (exact).
// If the full +-R window finishes with m > R^2, an exact full-column
// fallback fires (never on this data, but required for exactness).
// ---------------------------------------------------------------------------
#define TI 64
#define TJ 32
#define TY 8

__global__ void col_parabola_kernel(float* __restrict__ out) {
    __shared__ float s[TI + 2 * R][TJ];  // 96 x 32 floats = 12 KB

    const int j = blockIdx.x * TJ + threadIdx.x;   // column
    const int i0 = blockIdx.y * TI;                // base row of tile
    const int tx = threadIdx.x;                    // 0..31
    const int ty = threadIdx.y;                    // 0..7

    for (int r = ty; r < TI + 2 * R; r += TY) {
        const int gi = i0 + r - R;
        float v = BIGF;
        if (gi >= 0 && gi < H) v = g_f2[gi * W + j];
        s[r][tx] = v;
    }
    __syncthreads();

    #pragma unroll
    for (int rr = 0; rr < TI / TY; rr++) {
        const int li = ty + rr * TY;     // local row in [0, TI)
        const int i = i0 + li;

        float m = s[li + R][tx];         // d = 0 tap
        for (int d = 1; d <= R; d++) {
            if (__all_sync(0xffffffffu, m <= (float)(d * d))) break;
            const float dd = (float)(d * d);
            m = fminf(m, s[li + R - d][tx] + dd);
            m = fminf(m, s[li + R + d][tx] + dd);
        }

        if (m > (float)(R * R)) {
            // Exact fallback: full-column parabola min (rare).
            m = 3.4e38f;
            for (int k = 0; k < H; k++) {
                const float di = (float)(i - k);
                m = fminf(m, g_f2[k * W + j] + di * di);
            }
        }

        out[i * W + j] = sqrtf(m);
    }
}

// ---------------------------------------------------------------------------
extern "C" void kernel_launch(void* const* d_in, const int* in_sizes, int n_in,
                              void* d_out, int out_size) {
    const float* img = (const float*)d_in[0];
    float* out = (float*)d_out;

    row_dist_kernel<<<H, W>>>(img);

    dim3 block(TJ, TY);
    dim3 grid(W / TJ, H / TI);
    col_parabola_kernel<<<grid, block>>>(out);
}

// round 4
// speedup vs baseline: 1.5260x; 1.1104x over previous
#include <cuda_runtime.h>
#include <cuda_bf16.h>
#include <math.h>

#define H 1024
#define W 1024
#define BIGF 1e10f
#define SENT (1 << 30)

// Intermediate: per-row squared distance to nearest zero (pass 1 output)
__device__ float g_f2[H * W];

// ---------------------------------------------------------------------------
// Pass 1: one WARP per row, no __syncthreads.
// Each lane owns 32 consecutive pixels in registers. In-register serial
// nearest-zero-index scans (L->R max, R->L min), then one 5-step shfl scan
// per direction for the cross-lane carries. Matches reference int arithmetic.
// ---------------------------------------------------------------------------
__global__ void row_dist_kernel(const float* __restrict__ img) {
    const int warp = (blockIdx.x * blockDim.x + threadIdx.x) >> 5;
    const int lane = threadIdx.x & 31;
    const int row = warp;
    if (row >= H) return;

    const float4* __restrict__ img4 = (const float4*)(img + row * W);
    float4* __restrict__ out4 = (float4*)((float*)g_f2 + row * W);

    // Load 32 pixels (8 float4) for this lane.
    float4 v[8];
    #pragma unroll
    for (int q = 0; q < 8; q++) v[q] = img4[lane * 8 + q];

    const int base = lane * 32;

    // In-register serial scans of nearest-zero index.
    int zl[32], zr[32];
    {
        int last = -SENT;
        #pragma unroll
        for (int p = 0; p < 32; p++) {
            const float px = ((const float*)v)[p];
            if (px == 0.0f) last = base + p;
            zl[p] = last;
        }
        int nxt = SENT;
        #pragma unroll
        for (int p = 31; p >= 0; p--) {
            const float px = ((const float*)v)[p];
            if (px == 0.0f) nxt = base + p;
            zr[p] = nxt;
        }
    }

    // Cross-lane exclusive carries via shfl scans of lane aggregates.
    int a = zl[31];
    #pragma unroll
    for (int o = 1; o < 32; o <<= 1) {
        int t = __shfl_up_sync(0xffffffffu, a, o);
        if (lane >= o) a = max(a, t);
    }
    int carryL = __shfl_up_sync(0xffffffffu, a, 1);
    if (lane == 0) carryL = -SENT;

    int b = zr[0];
    #pragma unroll
    for (int o = 1; o < 32; o <<= 1) {
        int t = __shfl_down_sync(0xffffffffu, b, o);
        if (lane < 32 - o) b = min(b, t);
    }
    int carryR = __shfl_down_sync(0xffffffffu, b, 1);
    if (lane == 31) carryR = SENT;

    // Combine, square, store.
    #pragma unroll
    for (int q = 0; q < 8; q++) {
        float4 o4;
        #pragma unroll
        for (int c = 0; c < 4; c++) {
            const int p = q * 4 + c;
            const int idx = base + p;
            const int l = max(zl[p], carryL);
            const int r = min(zr[p], carryR);
            const int d = min(idx - l, r - idx);
            const float df = (float)d;
            ((float*)&o4)[c] = (d >= (1 << 29)) ? BIGF : df * df;
        }
        out4[lane * 8 + q] = o4;
    }
}

// ---------------------------------------------------------------------------
// Pass 2: out[i,j] = sqrt( min_k f2[k,j] + (i-k)^2 ).
// Branchless registerized +-8 window per pixel. Each thread handles 8
// CONSECUTIVE rows -> its 8 windows span 24 smem values, loaded once into
// registers; then 8 independent 17-tap fmin chains (pure register ILP).
// Exactness: if m <= 64 the window min is the global min (any |i-k|>8 gives
// (i-k)^2 >= 81 > 64 >= m). Otherwise (prob ~2^-17/pixel) exact full-column
// fallback.
// ---------------------------------------------------------------------------
#define TI 64
#define TJ 32
#define TY 8
#define HALO 8

__global__ void col_parabola_kernel(float* __restrict__ out) {
    __shared__ float s[TI + 2 * HALO][TJ];  // 80 x 32 = 10 KB

    const int tx = threadIdx.x;                    // 0..31 (column in tile)
    const int ty = threadIdx.y;                    // 0..7
    const int j = blockIdx.x * TJ + tx;
    const int i0 = blockIdx.y * TI;

    // Cooperative halo load (rows outside [0,H) padded with BIG).
    #pragma unroll
    for (int r = ty; r < TI + 2 * HALO; r += TY) {
        const int gi = i0 + r - HALO;
        float v = BIGF;
        if (gi >= 0 && gi < H) v = g_f2[gi * W + j];
        s[r][tx] = v;
    }
    __syncthreads();

    const int L = ty * 8;  // first local row owned by this thread

    // Registerize the 24-row span covering all 8 windows.
    float win[24];
    #pragma unroll
    for (int k = 0; k < 24; k++) win[k] = s[L + k][tx];

    // 8 independent min chains, interleaved for ILP.
    float m[8];
    #pragma unroll
    for (int u = 0; u < 8; u++) m[u] = win[u + 8];  // d = 0 tap
    #pragma unroll
    for (int d = 1; d <= 8; d++) {
        const float dd = (float)(d * d);
        #pragma unroll
        for (int u = 0; u < 8; u++) {
            m[u] = fminf(m[u], win[u + 8 - d] + dd);
            m[u] = fminf(m[u], win[u + 8 + d] + dd);
        }
    }

    #pragma unroll
    for (int u = 0; u < 8; u++) {
        const int i = i0 + L + u;
        float mv = m[u];
        if (mv > 64.0f) {
            // Exact fallback: full-column parabola min (astronomically rare).
            mv = 3.4e38f;
            for (int k = 0; k < H; k++) {
                const float di = (float)(i - k);
                mv = fminf(mv, g_f2[k * W + j] + di * di);
            }
        }
        out[i * W + j] = sqrtf(mv);
    }
}

// ---------------------------------------------------------------------------
extern "C" void kernel_launch(void* const* d_in, const int* in_sizes, int n_in,
                              void* d_out, int out_size) {
    const float* img = (const float*)d_in[0];
    float* out = (float*)d_out;

    // 1024 rows, one warp each: 256 blocks x 128 threads (4 warps).
    row_dist_kernel<<<256, 128>>>(img);

    dim3 block(TJ, TY);
    dim3 grid(W / TJ, H / TI);
    col_parabola_kernel<<<grid, block>>>(out);
}

// round 5
// speedup vs baseline: 2.1429x; 1.4043x over previous
#include <cuda_runtime.h>
#include <cuda_bf16.h>
#include <math.h>

#define H 1024
#define W 1024
#define BIGF 1e10f
#define SENT (1 << 30)

// Intermediate: per-row squared distance to nearest zero (pass 1 output)
__device__ float g_f2[H * W];

__device__ __forceinline__ float sqrt_approx(float x) {
    float r;
    asm("sqrt.approx.f32 %0, %1;" : "=f"(r) : "f"(x));
    return r;
}

// ---------------------------------------------------------------------------
// Pass 1: one WARP per row, no barriers, no register arrays.
// Each lane packs its 32 consecutive pixels into a uint32 zero-mask, finds
// nearest zero left/right per pixel with clz/ffs on masked bits, and gets
// cross-lane carries from two 5-step shfl scans of lane aggregates.
// Matches reference int arithmetic exactly.
// ---------------------------------------------------------------------------
__global__ void __launch_bounds__(256) row_dist_kernel(const float* __restrict__ img) {
    const int warp = (blockIdx.x * blockDim.x + threadIdx.x) >> 5;
    const int lane = threadIdx.x & 31;
    if (warp >= H) return;
    const int row = warp;

    const float4* __restrict__ img4 = (const float4*)(img + row * W);
    float4* __restrict__ out4 = (float4*)((float*)g_f2 + row * W);

    float4 v[8];
    #pragma unroll
    for (int q = 0; q < 8; q++) v[q] = img4[lane * 8 + q];

    unsigned mask = 0u;
    #pragma unroll
    for (int p = 0; p < 32; p++) {
        if (((const float*)v)[p] == 0.0f) mask |= (1u << p);
    }

    const int base = lane * 32;

    // Lane aggregates: index of last / first zero in this lane's 32 pixels.
    const int aggL = mask ? (base + 31 - __clz(mask)) : -SENT;
    const int aggR = mask ? (base + __ffs(mask) - 1) : SENT;

    // Exclusive cross-lane scans (max from left, min from right).
    int a = aggL;
    #pragma unroll
    for (int o = 1; o < 32; o <<= 1) {
        int t = __shfl_up_sync(0xffffffffu, a, o);
        if (lane >= o) a = max(a, t);
    }
    int carryL = __shfl_up_sync(0xffffffffu, a, 1);
    if (lane == 0) carryL = -SENT;

    int b = aggR;
    #pragma unroll
    for (int o = 1; o < 32; o <<= 1) {
        int t = __shfl_down_sync(0xffffffffu, b, o);
        if (lane < 32 - o) b = min(b, t);
    }
    int carryR = __shfl_down_sync(0xffffffffu, b, 1);
    if (lane == 31) carryR = SENT;

    #pragma unroll
    for (int q = 0; q < 8; q++) {
        float4 o4;
        #pragma unroll
        for (int c = 0; c < 4; c++) {
            const int p = q * 4 + c;
            const int idx = base + p;
            const unsigned ml = mask & (0xFFFFFFFFu >> (31 - p));
            const unsigned mr = mask & (0xFFFFFFFFu << p);
            const int zl = ml ? (base + 31 - __clz(ml)) : carryL;
            const int zr = mr ? (base + __ffs(mr) - 1) : carryR;
            const int d = min(idx - zl, zr - idx);
            const float df = (float)d;
            ((float*)&o4)[c] = (d >= (1 << 29)) ? BIGF : df * df;
        }
        out4[lane * 8 + q] = o4;
    }
}

// ---------------------------------------------------------------------------
// Pass 2: out[i,j] = sqrt( min_k f2[k,j] + (i-k)^2 ).
// No shared memory, no barrier: each thread loads its 24-row column window
// directly (L2-resident; warp-coalesced lines; 24 independent loads).
// Exactness: if m <= 64 the +-8 window min is the global min ((i-k)^2 >= 81
// outside). Otherwise (prob ~2^-17/pixel) exact full-column fallback.
// ---------------------------------------------------------------------------
__global__ void __launch_bounds__(256) col_parabola_kernel(float* __restrict__ out) {
    const int tx = threadIdx.x;          // 0..31: column within stripe
    const int ty = threadIdx.y;          // 0..7:  row group
    const int j = blockIdx.x * 32 + tx;
    const int ib = blockIdx.y * 64 + ty * 8;   // first of 8 rows owned

    float win[24];
    #pragma unroll
    for (int k = 0; k < 24; k++) {
        const int gi = ib - 8 + k;
        win[k] = (gi >= 0 && gi < H) ? g_f2[gi * W + j] : BIGF;
    }

    float m[8];
    #pragma unroll
    for (int u = 0; u < 8; u++) m[u] = win[u + 8];   // d = 0 tap
    #pragma unroll
    for (int d = 1; d <= 8; d++) {
        const float dd = (float)(d * d);
        #pragma unroll
        for (int u = 0; u < 8; u++) {
            m[u] = fminf(m[u], win[u + 8 - d] + dd);
            m[u] = fminf(m[u], win[u + 8 + d] + dd);
        }
    }

    #pragma unroll
    for (int u = 0; u < 8; u++) {
        const int i = ib + u;
        float mv = m[u];
        if (mv > 64.0f) {
            // Exact fallback: full-column parabola min (astronomically rare).
            mv = 3.4e38f;
            for (int k = 0; k < H; k++) {
                const float di = (float)(i - k);
                mv = fminf(mv, g_f2[k * W + j] + di * di);
            }
        }
        out[i * W + j] = sqrt_approx(mv);
    }
}

// ---------------------------------------------------------------------------
extern "C" void kernel_launch(void* const* d_in, const int* in_sizes, int n_in,
                              void* d_out, int out_size) {
    const float* img = (const float*)d_in[0];
    float* out = (float*)d_out;

    row_dist_kernel<<<128, 256>>>(img);          // 1024 warps, one per row

    dim3 block(32, 8);
    dim3 grid(W / 32, H / 64);                   // 32 x 16 = 512 CTAs
    col_parabola_kernel<<<grid, block>>>(out);
}